// round 10
// baseline (speedup 1.0000x reference)
#include <cuda_runtime.h>

// SE block, one persistent kernel, 456 blocks = 3 CTAs/SM x 512 threads
// (48 warps/SM resident vs 32 before -> +50% memory-level parallelism, and
// CTAs on one SM desynchronize across phases, mixing DRAM reads + writes).
// Per-batch arrival counters instead of a global barrier (replay-safe mod-256).
//
// Phase 1: quarter-plane units (98 float8), 256-bit evict_last loads
//          (pins x in L2; 103MB < 126MB).
// Phase 3: REVERSE streaming of the same chunk, __ldcs reads / __stcs writes,
//          4-wide unroll (fits the 42-reg budget of launch_bounds(512,3)).

#define C        256
#define BOT      32
#define HW       3136
#define HW4      784
#define QP8      98                  // float8 per quarter-plane unit
#define BC       8192
#define GRID     456
#define NTHREADS 512

__device__ float d_s[BC];                 // pooled means
__device__ unsigned int d_cnt[32];        // per-batch counters (never reset)

struct __align__(32) F8 { float4 a, b; };

__device__ __forceinline__ float ld8_el_sum(const F8* p) {
    unsigned r0, r1, r2, r3, r4, r5, r6, r7;
    asm volatile(
        "ld.global.nc.L2::evict_last.v8.b32 {%0,%1,%2,%3,%4,%5,%6,%7}, [%8];"
        : "=r"(r0), "=r"(r1), "=r"(r2), "=r"(r3),
          "=r"(r4), "=r"(r5), "=r"(r6), "=r"(r7)
        : "l"(p));
    float s0 = __uint_as_float(r0) + __uint_as_float(r1);
    float s1 = __uint_as_float(r2) + __uint_as_float(r3);
    float s2 = __uint_as_float(r4) + __uint_as_float(r5);
    float s3 = __uint_as_float(r6) + __uint_as_float(r7);
    return (s0 + s1) + (s2 + s3);
}

__global__ void __launch_bounds__(NTHREADS, 3) se_fused_kernel(
    const float* __restrict__ x,
    const float* __restrict__ w1, const float* __restrict__ b1,
    const float* __restrict__ w2, const float* __restrict__ b2,
    float* __restrict__ out)
{
    const int tid  = threadIdx.x;
    const int warp = tid >> 5;
    const int lane = tid & 31;
    const int bid  = blockIdx.x;

    const int p0 = (int)(((long long)bid * BC) / GRID);
    const int p1 = (int)(((long long)(bid + 1) * BC) / GRID);
    const int nk = p1 - p0;                  // 17 or 18 planes
    const int nu = nk * 4;                   // quarter-plane units (68/72)

    const int b0 = p0 >> 8;
    const int nb = ((p1 - 1) >> 8) - b0 + 1; // 1 or 2 batches touched
    const int n0 = min((b0 + 1) * C, p1) - p0;   // planes in batch b0
    const int n1 = nk - n0;                      // planes in batch b0+1

    __shared__ float sh_part[72];
    __shared__ float sh_s[2][C];
    __shared__ float sh_h[2][BOT];
    __shared__ float sh_g[20];

    // ------------- Phase 1: quarter-plane sums via 256-bit evict_last ---------
    const F8* __restrict__ xb8 =
        reinterpret_cast<const F8*>(x + (size_t)p0 * HW);
    for (int u = warp; u < nu; u += 16) {
        const F8* __restrict__ xp = xb8 + (size_t)u * QP8;
        // 98 = 3*32 + 2 : 3 unguarded + 1 predicated 32B load
        float s0 = ld8_el_sum(xp + lane);
        float s1 = ld8_el_sum(xp + lane + 32);
        float s2 = ld8_el_sum(xp + lane + 64);
        float s3 = (lane < 2) ? ld8_el_sum(xp + 96 + lane) : 0.0f;
        float sum = (s0 + s1) + (s2 + s3);
        #pragma unroll
        for (int o = 16; o > 0; o >>= 1)
            sum += __shfl_xor_sync(0xffffffffu, sum, o);
        if (lane == 0) sh_part[u] = sum;
    }
    __syncthreads();
    if (tid < nk) {
        const float* __restrict__ pp = sh_part + 4 * tid;
        d_s[p0 + tid] = ((pp[0] + pp[1]) + (pp[2] + pp[3])) * (1.0f / (float)HW);
    }
    __threadfence();                          // publish this thread's d_s write
    __syncthreads();

    // ------------- Per-batch arrive + wait (replay-safe, mod-256) -------------
    if (tid == 0) {
        atomicAdd(&d_cnt[b0], (unsigned)n0);
        if (n1 > 0) atomicAdd(&d_cnt[b0 + 1], (unsigned)n1);
        volatile unsigned int* vc = d_cnt;
        while (vc[b0] & 255u) __nanosleep(32);
        if (n1 > 0)
            while (vc[b0 + 1] & 255u) __nanosleep(32);
        __threadfence();
    }
    __syncthreads();

    // ---------------- Phase 2: means -> hidden -> gates for our chunk ---------
    for (int idx = tid; idx < nb * C; idx += NTHREADS)
        sh_s[idx >> 8][idx & 255] = d_s[b0 * C + idx];
    __syncthreads();

    for (int j = warp; j < nb * BOT; j += 16) {
        const int bi = j >> 5, o = j & 31;
        const float* __restrict__ w1row = w1 + o * C;
        float acc = 0.0f;
        #pragma unroll
        for (int k = 0; k < 8; k++) {
            const int c = lane + 32 * k;
            acc = fmaf(sh_s[bi][c], __ldg(w1row + c), acc);
        }
        #pragma unroll
        for (int off = 16; off > 0; off >>= 1)
            acc += __shfl_xor_sync(0xffffffffu, acc, off);
        if (lane == 0) sh_h[bi][o] = fmaxf(acc + __ldg(b1 + o), 0.0f);
    }
    __syncthreads();

    if (tid < nk) {
        const int plane = p0 + tid;
        const int c = plane & 255;
        const int bi = (plane >> 8) - b0;
        const float* __restrict__ wrow = w2 + c * BOT;
        float acc = __ldg(b2 + c);
        #pragma unroll
        for (int o = 0; o < BOT; o++)
            acc = fmaf(sh_h[bi][o], __ldg(wrow + o), acc);
        sh_g[tid] = 1.0f / (1.0f + __expf(-acc));
    }
    __syncthreads();

    // ---------------- Phase 3: REVERSE flat streaming, 4-wide -----------------
    const unsigned int total = (unsigned int)nk * HW4;       // <= 14112
    const int nfull = (int)(total / (4u * NTHREADS));        // full 4-wide iters
    const float4* __restrict__ x4 =
        reinterpret_cast<const float4*>(x) + (size_t)p0 * HW4;
    float4* __restrict__ o4 = reinterpret_cast<float4*>(out) + (size_t)p0 * HW4;

    // tail first (highest addresses = hottest in L1/L2)
    for (unsigned int i = (unsigned int)nfull * 4u * NTHREADS + tid; i < total;
         i += NTHREADS) {
        const float g = sh_g[i / HW4];
        float4 v = __ldcs(x4 + i);
        v.x *= g; v.y *= g; v.z *= g; v.w *= g;
        __stcs(o4 + i, v);
    }
    for (int it = nfull - 1; it >= 0; --it) {
        const unsigned int i = (unsigned int)it * 4u * NTHREADS + tid;
        float4 v0 = __ldcs(x4 + i);
        float4 v1 = __ldcs(x4 + i + 1 * NTHREADS);
        float4 v2 = __ldcs(x4 + i + 2 * NTHREADS);
        float4 v3 = __ldcs(x4 + i + 3 * NTHREADS);
        const float g0 = sh_g[(i) / HW4];
        const float g1 = sh_g[(i + 1 * NTHREADS) / HW4];
        const float g2 = sh_g[(i + 2 * NTHREADS) / HW4];
        const float g3 = sh_g[(i + 3 * NTHREADS) / HW4];
        v0.x *= g0; v0.y *= g0; v0.z *= g0; v0.w *= g0;
        v1.x *= g1; v1.y *= g1; v1.z *= g1; v1.w *= g1;
        v2.x *= g2; v2.y *= g2; v2.z *= g2; v2.w *= g2;
        v3.x *= g3; v3.y *= g3; v3.z *= g3; v3.w *= g3;
        __stcs(o4 + i,                v0);
        __stcs(o4 + i + 1 * NTHREADS, v1);
        __stcs(o4 + i + 2 * NTHREADS, v2);
        __stcs(o4 + i + 3 * NTHREADS, v3);
    }
}

extern "C" void kernel_launch(void* const* d_in, const int* in_sizes, int n_in,
                              void* d_out, int out_size) {
    const float* x  = (const float*)d_in[0];
    const float* w1 = (const float*)d_in[1];
    const float* b1 = (const float*)d_in[2];
    const float* w2 = (const float*)d_in[3];
    const float* b2 = (const float*)d_in[4];
    float* out = (float*)d_out;

    se_fused_kernel<<<GRID, NTHREADS>>>(x, w1, b1, w2, b2, out);
}